// round 2
// baseline (speedup 1.0000x reference)
#include <cuda_runtime.h>
#include <math.h>

// Problem dims (fixed by the benchmark)
#define LDIM 2048
#define BDIM 4
#define EDIM 1024
#define HDIM 16
#define DDIM 64
#define MROWS (LDIM * BDIM)   // 8192
#define E3    (3 * EDIM)      // 3072

// Scratch (allocation-free rule: __device__ globals)
__device__ float g_qkv[(size_t)MROWS * E3];    // [L*B, 3E], q pre-scaled
__device__ float g_attn[(size_t)MROWS * EDIM]; // [L*B, E]

// ---------------------------------------------------------------------------
// SGEMM: C[m,n] = sum_k A[m,k] * W[n,k] + bias[n], optional scaling of cols<SC
// A: [M,K] row-major, W: [N,K] row-major. 64x64 tile, 4x4 micro, BK=16.
// ---------------------------------------------------------------------------
template <int SCALE_COLS>
__global__ __launch_bounds__(256) void sgemm_abt(
    const float* __restrict__ A, const float* __restrict__ W,
    const float* __restrict__ bias, float* __restrict__ C,
    int Mn, int Nn, int Kn)
{
    __shared__ float As[16][65];
    __shared__ float Bs[16][65];

    const int tid = threadIdx.x;
    const int tx = tid & 15;
    const int ty = tid >> 4;
    const int n0 = blockIdx.x * 64;
    const int m0 = blockIdx.y * 64;

    const int lrow = tid >> 2;        // 0..63
    const int lc4  = (tid & 3) * 4;   // 0,4,8,12

    const float* Aptr = A + (size_t)(m0 + lrow) * Kn + lc4;
    const float* Wptr = W + (size_t)(n0 + lrow) * Kn + lc4;

    float acc[4][4] = {};

    for (int k0 = 0; k0 < Kn; k0 += 16) {
        float4 av = *(const float4*)(Aptr + k0);
        float4 bv = *(const float4*)(Wptr + k0);
        As[lc4 + 0][lrow] = av.x; As[lc4 + 1][lrow] = av.y;
        As[lc4 + 2][lrow] = av.z; As[lc4 + 3][lrow] = av.w;
        Bs[lc4 + 0][lrow] = bv.x; Bs[lc4 + 1][lrow] = bv.y;
        Bs[lc4 + 2][lrow] = bv.z; Bs[lc4 + 3][lrow] = bv.w;
        __syncthreads();

        #pragma unroll
        for (int k = 0; k < 16; k++) {
            float ar[4], br[4];
            #pragma unroll
            for (int i = 0; i < 4; i++) ar[i] = As[k][ty * 4 + i];
            #pragma unroll
            for (int j = 0; j < 4; j++) br[j] = Bs[k][tx * 4 + j];
            #pragma unroll
            for (int i = 0; i < 4; i++)
                #pragma unroll
                for (int j = 0; j < 4; j++)
                    acc[i][j] = fmaf(ar[i], br[j], acc[i][j]);
        }
        __syncthreads();
    }

    const int nbase = n0 + tx * 4;
    #pragma unroll
    for (int i = 0; i < 4; i++) {
        float4 v;
        float* vp = &v.x;
        #pragma unroll
        for (int j = 0; j < 4; j++) {
            int n = nbase + j;
            float r = acc[i][j] + bias[n];
            if (SCALE_COLS > 0 && n < SCALE_COLS) r *= 0.125f;  // D^-0.5
            vp[j] = r;
        }
        *(float4*)(C + (size_t)(m0 + ty * 4 + i) * Nn + nbase) = v;
    }
}

// ---------------------------------------------------------------------------
// Flash attention, fp32. One block = 64 query rows of one (b,h).
// qkv layout: [(l*B+b), 3E] with q at +0, k at +E, v at +2E, head h at h*64.
// ---------------------------------------------------------------------------
__global__ __launch_bounds__(256) void attn_flash(
    const float* __restrict__ qkv, const unsigned char* __restrict__ kpm,
    float* __restrict__ outp)
{
    extern __shared__ float sm[];
    float* Qs = sm;                 // [64][65]
    float* Ks = Qs + 64 * 65;
    float* Vs = Ks + 64 * 65;
    float* Ps = Vs + 64 * 65;
    __shared__ unsigned char msk[64];

    const int tid = threadIdx.x;
    const int tx = tid & 15;
    const int ty = tid >> 4;
    const int m0 = blockIdx.x * 64;
    const int bh = blockIdx.y;
    const int b = bh >> 4;          // / HDIM
    const int h = bh & 15;          // % HDIM
    const int hoff = h * 64;

    // Load Q tile (already scaled by D^-0.5 in the QKV GEMM epilogue)
    #pragma unroll
    for (int p = 0; p < 4; p++) {
        int idx = tid + p * 256;            // 0..1023
        int r  = idx >> 4;
        int c4 = (idx & 15) * 4;
        int l  = m0 + r;
        float4 v = *(const float4*)(qkv + (size_t)(l * BDIM + b) * E3 + hoff + c4);
        Qs[r * 65 + c4 + 0] = v.x; Qs[r * 65 + c4 + 1] = v.y;
        Qs[r * 65 + c4 + 2] = v.z; Qs[r * 65 + c4 + 3] = v.w;
    }

    float m_i[4], l_i[4], O[4][4];
    #pragma unroll
    for (int i = 0; i < 4; i++) {
        m_i[i] = -INFINITY; l_i[i] = 0.f;
        #pragma unroll
        for (int j = 0; j < 4; j++) O[i][j] = 0.f;
    }
    __syncthreads();

    for (int t = 0; t < LDIM / 64; t++) {
        const int s0 = t * 64;
        // Load K,V tiles
        #pragma unroll
        for (int p = 0; p < 4; p++) {
            int idx = tid + p * 256;
            int r  = idx >> 4;
            int c4 = (idx & 15) * 4;
            size_t base = (size_t)((s0 + r) * BDIM + b) * E3 + hoff + c4;
            float4 kv = *(const float4*)(qkv + base + EDIM);
            float4 vv = *(const float4*)(qkv + base + 2 * EDIM);
            Ks[r * 65 + c4 + 0] = kv.x; Ks[r * 65 + c4 + 1] = kv.y;
            Ks[r * 65 + c4 + 2] = kv.z; Ks[r * 65 + c4 + 3] = kv.w;
            Vs[r * 65 + c4 + 0] = vv.x; Vs[r * 65 + c4 + 1] = vv.y;
            Vs[r * 65 + c4 + 2] = vv.z; Vs[r * 65 + c4 + 3] = vv.w;
        }
        if (tid < 64) msk[tid] = kpm[(size_t)(s0 + tid) * BDIM + b];
        __syncthreads();

        // S = Q * K^T  (4x4 per thread)
        float acc[4][4] = {};
        #pragma unroll 16
        for (int d = 0; d < 64; d++) {
            float qr[4], kr[4];
            #pragma unroll
            for (int i = 0; i < 4; i++) qr[i] = Qs[(ty * 4 + i) * 65 + d];
            #pragma unroll
            for (int j = 0; j < 4; j++) kr[j] = Ks[(tx * 4 + j) * 65 + d];
            #pragma unroll
            for (int i = 0; i < 4; i++)
                #pragma unroll
                for (int j = 0; j < 4; j++)
                    acc[i][j] = fmaf(qr[i], kr[j], acc[i][j]);
        }

        // key padding mask
        #pragma unroll
        for (int j = 0; j < 4; j++)
            if (msk[tx * 4 + j])
                #pragma unroll
                for (int i = 0; i < 4; i++) acc[i][j] = -INFINITY;

        // online softmax per row (reduce across the 16 tx lanes)
        float pr[4][4], scl[4];
        #pragma unroll
        for (int i = 0; i < 4; i++) {
            float mx = acc[i][0];
            #pragma unroll
            for (int j = 1; j < 4; j++) mx = fmaxf(mx, acc[i][j]);
            #pragma unroll
            for (int o = 8; o > 0; o >>= 1)
                mx = fmaxf(mx, __shfl_xor_sync(0xffffffffu, mx, o));
            float mnew = fmaxf(m_i[i], mx);
            float mref = (mnew == -INFINITY) ? 0.f : mnew;  // guard all-masked rows
            float sum = 0.f;
            #pragma unroll
            for (int j = 0; j < 4; j++) {
                float p = __expf(acc[i][j] - mref);
                pr[i][j] = p; sum += p;
            }
            #pragma unroll
            for (int o = 8; o > 0; o >>= 1)
                sum += __shfl_xor_sync(0xffffffffu, sum, o);
            float sc = __expf(m_i[i] - mref);
            if (m_i[i] == -INFINITY) sc = 0.f;
            l_i[i] = l_i[i] * sc + sum;
            m_i[i] = mnew;
            scl[i] = sc;
        }

        // store P, rescale O
        #pragma unroll
        for (int i = 0; i < 4; i++) {
            #pragma unroll
            for (int j = 0; j < 4; j++) {
                Ps[(ty * 4 + i) * 65 + tx * 4 + j] = pr[i][j];
                O[i][j] *= scl[i];
            }
        }
        __syncthreads();

        // O += P * V
        #pragma unroll 8
        for (int j = 0; j < 64; j++) {
            float pv[4], vv[4];
            #pragma unroll
            for (int i = 0; i < 4; i++) pv[i] = Ps[(ty * 4 + i) * 65 + j];
            #pragma unroll
            for (int jj = 0; jj < 4; jj++) vv[jj] = Vs[j * 65 + tx * 4 + jj];
            #pragma unroll
            for (int i = 0; i < 4; i++)
                #pragma unroll
                for (int jj = 0; jj < 4; jj++)
                    O[i][jj] = fmaf(pv[i], vv[jj], O[i][jj]);
        }
        __syncthreads();
    }

    // normalize + write [L*B, E] at head offset
    #pragma unroll
    for (int i = 0; i < 4; i++) {
        float inv = 1.0f / l_i[i];
        int l = m0 + ty * 4 + i;
        float4 v;
        v.x = O[i][0] * inv; v.y = O[i][1] * inv;
        v.z = O[i][2] * inv; v.w = O[i][3] * inv;
        *(float4*)(outp + (size_t)(l * BDIM + b) * EDIM + hoff + tx * 4) = v;
    }
}

// ---------------------------------------------------------------------------
extern "C" void kernel_launch(void* const* d_in, const int* in_sizes, int n_in,
                              void* d_out, int out_size)
{
    const float* x    = (const float*)d_in[0];
    const float* win  = (const float*)d_in[1];
    const float* bin  = (const float*)d_in[2];
    const float* wout = (const float*)d_in[3];
    const float* bout = (const float*)d_in[4];
    const unsigned char* kpm = (const unsigned char*)d_in[5];
    float* out = (float*)d_out;

    float *qkv_ptr, *attn_ptr;
    cudaGetSymbolAddress((void**)&qkv_ptr,  g_qkv);
    cudaGetSymbolAddress((void**)&attn_ptr, g_attn);

    // 1) QKV projection (q pre-scaled by D^-0.5 in epilogue)
    {
        dim3 grid(E3 / 64, MROWS / 64);
        sgemm_abt<EDIM><<<grid, 256>>>(x, win, bin, qkv_ptr, MROWS, E3, EDIM);
    }

    // 2) Flash attention
    {
        int smem = 4 * 64 * 65 * (int)sizeof(float);  // 66560 B
        cudaFuncSetAttribute(attn_flash, cudaFuncAttributeMaxDynamicSharedMemorySize, smem);
        dim3 grid(LDIM / 64, BDIM * HDIM);
        attn_flash<<<grid, 256, smem>>>(qkv_ptr, kpm, attn_ptr);
    }

    // 3) Output projection
    {
        dim3 grid(EDIM / 64, MROWS / 64);
        sgemm_abt<0><<<grid, 256>>>(attn_ptr, wout, bout, out, MROWS, EDIM, EDIM);
    }
}

// round 7
// speedup vs baseline: 1.4379x; 1.4379x over previous
#include <cuda_runtime.h>
#include <math.h>
#include <stdint.h>

// Problem dims (fixed by the benchmark)
#define LDIM 2048
#define BDIM 4
#define EDIM 1024
#define HDIM 16
#define DDIM 64
#define MROWS (LDIM * BDIM)   // 8192
#define E3    (3 * EDIM)      // 3072

// Scratch (allocation-free rule: __device__ globals)
__device__ float g_qkv[(size_t)MROWS * E3];    // [L*B, 3E], q pre-scaled
__device__ float g_attn[(size_t)MROWS * EDIM]; // [L*B, E]

// ---------------------------------------------------------------------------
// tf32 helpers
// ---------------------------------------------------------------------------
__device__ __forceinline__ uint32_t f2tf(float f) {
    uint32_t u;
    asm("cvt.rna.tf32.f32 %0, %1;" : "=r"(u) : "f"(f));
    return u;
}

__device__ __forceinline__ void mma_tf32(float c[4],
    uint32_t a0, uint32_t a1, uint32_t a2, uint32_t a3,
    uint32_t b0, uint32_t b1)
{
    asm volatile(
        "mma.sync.aligned.m16n8k8.row.col.f32.tf32.tf32.f32 "
        "{%0,%1,%2,%3}, {%4,%5,%6,%7}, {%8,%9}, {%0,%1,%2,%3};\n"
        : "+f"(c[0]), "+f"(c[1]), "+f"(c[2]), "+f"(c[3])
        : "r"(a0), "r"(a1), "r"(a2), "r"(a3), "r"(b0), "r"(b1));
}

// ---------------------------------------------------------------------------
// SGEMM (fp32, unchanged from R1): C[m,n] = sum_k A[m,k]*W[n,k] + bias[n]
// ---------------------------------------------------------------------------
template <int SCALE_COLS>
__global__ __launch_bounds__(256) void sgemm_abt(
    const float* __restrict__ A, const float* __restrict__ W,
    const float* __restrict__ bias, float* __restrict__ C,
    int Mn, int Nn, int Kn)
{
    __shared__ float As[16][65];
    __shared__ float Bs[16][65];

    const int tid = threadIdx.x;
    const int tx = tid & 15;
    const int ty = tid >> 4;
    const int n0 = blockIdx.x * 64;
    const int m0 = blockIdx.y * 64;

    const int lrow = tid >> 2;
    const int lc4  = (tid & 3) * 4;

    const float* Aptr = A + (size_t)(m0 + lrow) * Kn + lc4;
    const float* Wptr = W + (size_t)(n0 + lrow) * Kn + lc4;

    float acc[4][4] = {};

    for (int k0 = 0; k0 < Kn; k0 += 16) {
        float4 av = *(const float4*)(Aptr + k0);
        float4 bv = *(const float4*)(Wptr + k0);
        As[lc4 + 0][lrow] = av.x; As[lc4 + 1][lrow] = av.y;
        As[lc4 + 2][lrow] = av.z; As[lc4 + 3][lrow] = av.w;
        Bs[lc4 + 0][lrow] = bv.x; Bs[lc4 + 1][lrow] = bv.y;
        Bs[lc4 + 2][lrow] = bv.z; Bs[lc4 + 3][lrow] = bv.w;
        __syncthreads();

        #pragma unroll
        for (int k = 0; k < 16; k++) {
            float ar[4], br[4];
            #pragma unroll
            for (int i = 0; i < 4; i++) ar[i] = As[k][ty * 4 + i];
            #pragma unroll
            for (int j = 0; j < 4; j++) br[j] = Bs[k][tx * 4 + j];
            #pragma unroll
            for (int i = 0; i < 4; i++)
                #pragma unroll
                for (int j = 0; j < 4; j++)
                    acc[i][j] = fmaf(ar[i], br[j], acc[i][j]);
        }
        __syncthreads();
    }

    const int nbase = n0 + tx * 4;
    #pragma unroll
    for (int i = 0; i < 4; i++) {
        float4 v;
        float* vp = &v.x;
        #pragma unroll
        for (int j = 0; j < 4; j++) {
            int n = nbase + j;
            float r = acc[i][j] + bias[n];
            if (SCALE_COLS > 0 && n < SCALE_COLS) r *= 0.125f;  // D^-0.5
            vp[j] = r;
        }
        *(float4*)(C + (size_t)(m0 + ty * 4 + i) * Nn + nbase) = v;
    }
}

// ---------------------------------------------------------------------------
// Flash attention with tf32 mma.sync tensor cores.
// One CTA = 128 query rows of one (b,h). 8 warps, each owns 16 q rows.
// Iterate keys in chunks of 64. smem strides padded to 68 (conflict-free
// fragment loads: bank = 4*row + col covers all 32 banks).
//
// Fragment layouts (m16n8k8 tf32): gr = lane>>2, tg = lane&3
//   A (16x8 row):  a0=(gr,tg) a1=(gr+8,tg) a2=(gr,tg+4) a3=(gr+8,tg+4)
//   B (8x8 col):   b0=(k=tg, n=gr) b1=(k=tg+4, n=gr)
//   C (16x8):      c0=(gr,2tg) c1=(gr,2tg+1) c2=(gr+8,2tg) c3=(gr+8,2tg+1)
// ---------------------------------------------------------------------------
#define QS_STRIDE 68

__global__ __launch_bounds__(256) void attn_tf32(
    const float* __restrict__ qkv, const unsigned char* __restrict__ kpm,
    float* __restrict__ outp)
{
    extern __shared__ uint32_t sm[];
    uint32_t* Qs  = sm;                      // [128][68] tf32 bits
    uint32_t* Ks  = Qs  + 128 * QS_STRIDE;   // [64][68]  key-major
    uint32_t* Vst = Ks  +  64 * QS_STRIDE;   // [64][68]  d-major (V transposed)
    uint32_t* Ps  = Vst +  64 * QS_STRIDE;   // [128][68]
    float* maskAdd = (float*)(Ps + 128 * QS_STRIDE);  // [64]

    const int tid  = threadIdx.x;
    const int w    = tid >> 5;
    const int lane = tid & 31;
    const int gr   = lane >> 2;
    const int tg   = lane & 3;
    const int q0   = w * 16;
    const int m0   = blockIdx.x * 128;
    const int bh   = blockIdx.y;
    const int b    = bh >> 4;
    const int h    = bh & 15;
    const int hoff = h * 64;

    // ---- stage Q (tf32-rounded); q pre-scaled by D^-0.5 in projection ----
    #pragma unroll
    for (int p = 0; p < 8; p++) {
        int idx = tid + p * 256;              // 0..2047  (128 rows x 16 f4)
        int r = idx >> 4, c4 = (idx & 15) * 4;
        float4 v = *(const float4*)(qkv + (size_t)((m0 + r) * BDIM + b) * E3 + hoff + c4);
        Qs[r * QS_STRIDE + c4 + 0] = f2tf(v.x);
        Qs[r * QS_STRIDE + c4 + 1] = f2tf(v.y);
        Qs[r * QS_STRIDE + c4 + 2] = f2tf(v.z);
        Qs[r * QS_STRIDE + c4 + 3] = f2tf(v.w);
    }

    float o[8][4] = {};
    float m_lo = -INFINITY, m_hi = -INFINITY;
    float l_lo = 0.f, l_hi = 0.f;

    for (int t = 0; t < LDIM / 64; t++) {
        const int s0 = t * 64;

        __syncthreads();   // previous iter's reads of Ks/Vst complete

        // ---- stage K (key-major) and V (transposed, d-major) ----
        #pragma unroll
        for (int p = 0; p < 4; p++) {
            int idx = tid + p * 256;           // 0..1023 (64 rows x 16 f4)
            int r = idx >> 4, c4 = (idx & 15) * 4;
            size_t base = (size_t)((s0 + r) * BDIM + b) * E3 + hoff + c4;
            float4 kv = *(const float4*)(qkv + base + EDIM);
            float4 vv = *(const float4*)(qkv + base + 2 * EDIM);
            Ks[r * QS_STRIDE + c4 + 0] = f2tf(kv.x);
            Ks[r * QS_STRIDE + c4 + 1] = f2tf(kv.y);
            Ks[r * QS_STRIDE + c4 + 2] = f2tf(kv.z);
            Ks[r * QS_STRIDE + c4 + 3] = f2tf(kv.w);
            Vst[(c4 + 0) * QS_STRIDE + r] = f2tf(vv.x);
            Vst[(c4 + 1) * QS_STRIDE + r] = f2tf(vv.y);
            Vst[(c4 + 2) * QS_STRIDE + r] = f2tf(vv.z);
            Vst[(c4 + 3) * QS_STRIDE + r] = f2tf(vv.w);
        }
        if (tid < 64)
            maskAdd[tid] = kpm[(size_t)(s0 + tid) * BDIM + b] ? -INFINITY : 0.f;
        __syncthreads();

        // ---- S = Q K^T : m16 x n64 x k64 per warp ----
        float c[8][4] = {};
        #pragma unroll
        for (int k8 = 0; k8 < 64; k8 += 8) {
            uint32_t a0 = Qs[(q0 + gr)     * QS_STRIDE + k8 + tg];
            uint32_t a1 = Qs[(q0 + gr + 8) * QS_STRIDE + k8 + tg];
            uint32_t a2 = Qs[(q0 + gr)     * QS_STRIDE + k8 + tg + 4];
            uint32_t a3 = Qs[(q0 + gr + 8) * QS_STRIDE + k8 + tg + 4];
            #pragma unroll
            for (int j = 0; j < 8; j++) {
                uint32_t b0 = Ks[(8 * j + gr) * QS_STRIDE + k8 + tg];
                uint32_t b1 = Ks[(8 * j + gr) * QS_STRIDE + k8 + tg + 4];
                mma_tf32(c[j], a0, a1, a2, a3, b0, b1);
            }
        }

        // ---- key-padding mask ----
        #pragma unroll
        for (int j = 0; j < 8; j++) {
            float ma0 = maskAdd[8 * j + 2 * tg];
            float ma1 = maskAdd[8 * j + 2 * tg + 1];
            c[j][0] += ma0; c[j][1] += ma1;
            c[j][2] += ma0; c[j][3] += ma1;
        }

        // ---- online softmax (rows gr and gr+8; stats shared across quad) ----
        float mx_lo = -INFINITY, mx_hi = -INFINITY;
        #pragma unroll
        for (int j = 0; j < 8; j++) {
            mx_lo = fmaxf(mx_lo, fmaxf(c[j][0], c[j][1]));
            mx_hi = fmaxf(mx_hi, fmaxf(c[j][2], c[j][3]));
        }
        mx_lo = fmaxf(mx_lo, __shfl_xor_sync(0xffffffffu, mx_lo, 1));
        mx_lo = fmaxf(mx_lo, __shfl_xor_sync(0xffffffffu, mx_lo, 2));
        mx_hi = fmaxf(mx_hi, __shfl_xor_sync(0xffffffffu, mx_hi, 1));
        mx_hi = fmaxf(mx_hi, __shfl_xor_sync(0xffffffffu, mx_hi, 2));

        float mn_lo = fmaxf(m_lo, mx_lo);
        float mn_hi = fmaxf(m_hi, mx_hi);
        float mr_lo = (mn_lo == -INFINITY) ? 0.f : mn_lo;
        float mr_hi = (mn_hi == -INFINITY) ? 0.f : mn_hi;

        float sum_lo = 0.f, sum_hi = 0.f;
        #pragma unroll
        for (int j = 0; j < 8; j++) {
            float p0 = __expf(c[j][0] - mr_lo);
            float p1 = __expf(c[j][1] - mr_lo);
            float p2 = __expf(c[j][2] - mr_hi);
            float p3 = __expf(c[j][3] - mr_hi);
            sum_lo += p0 + p1;
            sum_hi += p2 + p3;
            uint2 lo; lo.x = f2tf(p0); lo.y = f2tf(p1);
            *(uint2*)&Ps[(q0 + gr)     * QS_STRIDE + 8 * j + 2 * tg] = lo;
            uint2 hi; hi.x = f2tf(p2); hi.y = f2tf(p3);
            *(uint2*)&Ps[(q0 + gr + 8) * QS_STRIDE + 8 * j + 2 * tg] = hi;
        }
        sum_lo += __shfl_xor_sync(0xffffffffu, sum_lo, 1);
        sum_lo += __shfl_xor_sync(0xffffffffu, sum_lo, 2);
        sum_hi += __shfl_xor_sync(0xffffffffu, sum_hi, 1);
        sum_hi += __shfl_xor_sync(0xffffffffu, sum_hi, 2);

        float sc_lo = (m_lo == -INFINITY) ? 0.f : __expf(m_lo - mr_lo);
        float sc_hi = (m_hi == -INFINITY) ? 0.f : __expf(m_hi - mr_hi);
        l_lo = l_lo * sc_lo + sum_lo;
        l_hi = l_hi * sc_hi + sum_hi;
        m_lo = mn_lo;
        m_hi = mn_hi;

        #pragma unroll
        for (int j = 0; j < 8; j++) {
            o[j][0] *= sc_lo; o[j][1] *= sc_lo;
            o[j][2] *= sc_hi; o[j][3] *= sc_hi;
        }
        __syncwarp();   // Ps stores visible to all lanes of this warp

        // ---- O += P V : m16 x n64 x k64 per warp ----
        #pragma unroll
        for (int k8 = 0; k8 < 64; k8 += 8) {
            uint32_t a0 = Ps[(q0 + gr)     * QS_STRIDE + k8 + tg];
            uint32_t a1 = Ps[(q0 + gr + 8) * QS_STRIDE + k8 + tg];
            uint32_t a2 = Ps[(q0 + gr)     * QS_STRIDE + k8 + tg + 4];
            uint32_t a3 = Ps[(q0 + gr + 8) * QS_STRIDE + k8 + tg + 4];
            #pragma unroll
            for (int j = 0; j < 8; j++) {
                uint32_t b0 = Vst[(8 * j + gr) * QS_STRIDE + k8 + tg];
                uint32_t b1 = Vst[(8 * j + gr) * QS_STRIDE + k8 + tg + 4];
                mma_tf32(o[j], a0, a1, a2, a3, b0, b1);
            }
        }
    }

    // ---- normalize + write out [L*B, E] at head offset ----
    float il_lo = 1.f / l_lo;
    float il_hi = 1.f / l_hi;
    #pragma unroll
    for (int j = 0; j < 8; j++) {
        float2 vlo = make_float2(o[j][0] * il_lo, o[j][1] * il_lo);
        *(float2*)(outp + (size_t)((m0 + q0 + gr) * BDIM + b) * EDIM
                   + hoff + 8 * j + 2 * tg) = vlo;
        float2 vhi = make_float2(o[j][2] * il_hi, o[j][3] * il_hi);
        *(float2*)(outp + (size_t)((m0 + q0 + gr + 8) * BDIM + b) * EDIM
                   + hoff + 8 * j + 2 * tg) = vhi;
    }
}

// ---------------------------------------------------------------------------
extern "C" void kernel_launch(void* const* d_in, const int* in_sizes, int n_in,
                              void* d_out, int out_size)
{
    const float* x    = (const float*)d_in[0];
    const float* win  = (const float*)d_in[1];
    const float* bin  = (const float*)d_in[2];
    const float* wout = (const float*)d_in[3];
    const float* bout = (const float*)d_in[4];
    const unsigned char* kpm = (const unsigned char*)d_in[5];
    float* out = (float*)d_out;

    float *qkv_ptr, *attn_ptr;
    cudaGetSymbolAddress((void**)&qkv_ptr,  g_qkv);
    cudaGetSymbolAddress((void**)&attn_ptr, g_attn);

    // 1) QKV projection (q pre-scaled by D^-0.5 in epilogue)
    {
        dim3 grid(E3 / 64, MROWS / 64);
        sgemm_abt<EDIM><<<grid, 256>>>(x, win, bin, qkv_ptr, MROWS, E3, EDIM);
    }

    // 2) Flash attention (tf32 tensor cores)
    {
        int smem = (128 * QS_STRIDE + 64 * QS_STRIDE + 64 * QS_STRIDE
                    + 128 * QS_STRIDE) * (int)sizeof(uint32_t)
                   + 64 * (int)sizeof(float);   // 104704 B
        cudaFuncSetAttribute(attn_tf32, cudaFuncAttributeMaxDynamicSharedMemorySize, smem);
        dim3 grid(LDIM / 128, BDIM * HDIM);
        attn_tf32<<<grid, 256, smem>>>(qkv_ptr, kpm, attn_ptr);
    }

    // 3) Output projection
    {
        dim3 grid(EDIM / 64, MROWS / 64);
        sgemm_abt<0><<<grid, 256>>>(attn_ptr, wout, bout, out, MROWS, EDIM, EDIM);
    }
}

// round 10
// speedup vs baseline: 3.5522x; 2.4704x over previous
#include <cuda_runtime.h>
#include <math.h>
#include <stdint.h>

// Problem dims (fixed by the benchmark)
#define LDIM 2048
#define BDIM 4
#define EDIM 1024
#define HDIM 16
#define DDIM 64
#define MROWS (LDIM * BDIM)   // 8192
#define E3    (3 * EDIM)      // 3072

// Scratch (allocation-free rule: __device__ globals)
__device__ float g_qkv[(size_t)MROWS * E3];    // [L*B, 3E], q pre-scaled
__device__ float g_attn[(size_t)MROWS * EDIM]; // [L*B, E]

// ---------------------------------------------------------------------------
// tf32 helpers
// ---------------------------------------------------------------------------
__device__ __forceinline__ uint32_t f2tf(float f) {
    uint32_t u;
    asm("cvt.rna.tf32.f32 %0, %1;" : "=r"(u) : "f"(f));
    return u;
}

__device__ __forceinline__ void mma_tf32(float c[4],
    uint32_t a0, uint32_t a1, uint32_t a2, uint32_t a3,
    uint32_t b0, uint32_t b1)
{
    asm volatile(
        "mma.sync.aligned.m16n8k8.row.col.f32.tf32.tf32.f32 "
        "{%0,%1,%2,%3}, {%4,%5,%6,%7}, {%8,%9}, {%0,%1,%2,%3};\n"
        : "+f"(c[0]), "+f"(c[1]), "+f"(c[2]), "+f"(c[3])
        : "r"(a0), "r"(a1), "r"(a2), "r"(a3), "r"(b0), "r"(b1));
}

// ---------------------------------------------------------------------------
// tf32 tensor GEMM: C[m,n] = sum_k A[m,k]*W[n,k] + bias[n]
// A: [M,K] row-major, W: [N,K] row-major (both K-major -> row.col mma).
// CTA tile 128x128, BK=16, 8 warps each m64 x n32. Double-buffered smem,
// stride 20 (=4 mod 32) -> conflict-free fragment loads, 16B-aligned rows.
// ---------------------------------------------------------------------------
#define GS 20

template <int SCALE_COLS>
__global__ __launch_bounds__(256) void gemm_tf32(
    const float* __restrict__ A, const float* __restrict__ W,
    const float* __restrict__ bias, float* __restrict__ C,
    int Nn, int Kn)
{
    __shared__ uint32_t As[2][128 * GS];
    __shared__ uint32_t Bs[2][128 * GS];

    const int tid  = threadIdx.x;
    const int w    = tid >> 5;
    const int lane = tid & 31;
    const int gr   = lane >> 2;
    const int tg   = lane & 3;
    const int wm   = (w >> 2) * 64;   // 0 or 64
    const int wn   = (w & 3) * 32;    // 0,32,64,96
    const int n0   = blockIdx.x * 128;
    const int m0   = blockIdx.y * 128;

    // staging: each thread owns 2 float4 of A and 2 of B per BK16 tile
    const int r0 = tid >> 2;              // 0..63
    const int r1 = r0 + 64;               // 64..127
    const int c4 = (tid & 3) * 4;         // 0,4,8,12

    const float* Ap0 = A + (size_t)(m0 + r0) * Kn + c4;
    const float* Ap1 = A + (size_t)(m0 + r1) * Kn + c4;
    const float* Wp0 = W + (size_t)(n0 + r0) * Kn + c4;
    const float* Wp1 = W + (size_t)(n0 + r1) * Kn + c4;

    float acc[4][4][4] = {};

    const int nK = Kn >> 4;
    float4 av0 = *(const float4*)Ap0;
    float4 av1 = *(const float4*)Ap1;
    float4 wv0 = *(const float4*)Wp0;
    float4 wv1 = *(const float4*)Wp1;

    for (int kt = 0; kt < nK; kt++) {
        const int buf = kt & 1;
        // stage (convert to tf32, STS.128 via uint4)
        {
            uint4 u;
            u.x = f2tf(av0.x); u.y = f2tf(av0.y); u.z = f2tf(av0.z); u.w = f2tf(av0.w);
            *(uint4*)&As[buf][r0 * GS + c4] = u;
            u.x = f2tf(av1.x); u.y = f2tf(av1.y); u.z = f2tf(av1.z); u.w = f2tf(av1.w);
            *(uint4*)&As[buf][r1 * GS + c4] = u;
            u.x = f2tf(wv0.x); u.y = f2tf(wv0.y); u.z = f2tf(wv0.z); u.w = f2tf(wv0.w);
            *(uint4*)&Bs[buf][r0 * GS + c4] = u;
            u.x = f2tf(wv1.x); u.y = f2tf(wv1.y); u.z = f2tf(wv1.z); u.w = f2tf(wv1.w);
            *(uint4*)&Bs[buf][r1 * GS + c4] = u;
        }
        __syncthreads();

        // prefetch next BK16 tile
        if (kt + 1 < nK) {
            const int ko = (kt + 1) << 4;
            av0 = *(const float4*)(Ap0 + ko);
            av1 = *(const float4*)(Ap1 + ko);
            wv0 = *(const float4*)(Wp0 + ko);
            wv1 = *(const float4*)(Wp1 + ko);
        }

        // compute: 2 k8 steps
        #pragma unroll
        for (int k8 = 0; k8 < 16; k8 += 8) {
            uint32_t a[4][4], bfr[4][2];
            #pragma unroll
            for (int i = 0; i < 4; i++) {
                const int mr = wm + 16 * i + gr;
                a[i][0] = As[buf][(mr)     * GS + k8 + tg];
                a[i][1] = As[buf][(mr + 8) * GS + k8 + tg];
                a[i][2] = As[buf][(mr)     * GS + k8 + tg + 4];
                a[i][3] = As[buf][(mr + 8) * GS + k8 + tg + 4];
            }
            #pragma unroll
            for (int j = 0; j < 4; j++) {
                const int nr = wn + 8 * j + gr;
                bfr[j][0] = Bs[buf][nr * GS + k8 + tg];
                bfr[j][1] = Bs[buf][nr * GS + k8 + tg + 4];
            }
            #pragma unroll
            for (int i = 0; i < 4; i++)
                #pragma unroll
                for (int j = 0; j < 4; j++)
                    mma_tf32(acc[i][j], a[i][0], a[i][1], a[i][2], a[i][3],
                             bfr[j][0], bfr[j][1]);
        }
        // single sync per iter: next STS targets the other buffer
    }

    // epilogue: bias + optional q-scaling, float2 stores
    #pragma unroll
    for (int i = 0; i < 4; i++) {
        const int row = m0 + wm + 16 * i + gr;
        #pragma unroll
        for (int j = 0; j < 4; j++) {
            const int col = n0 + wn + 8 * j + 2 * tg;
            const float b0v = bias[col], b1v = bias[col + 1];
            float s = (SCALE_COLS > 0 && col < SCALE_COLS) ? 0.125f : 1.0f;
            float2 lo = make_float2((acc[i][j][0] + b0v) * s,
                                    (acc[i][j][1] + b1v) * s);
            float2 hi = make_float2((acc[i][j][2] + b0v) * s,
                                    (acc[i][j][3] + b1v) * s);
            *(float2*)(C + (size_t)row * Nn + col) = lo;
            *(float2*)(C + (size_t)(row + 8) * Nn + col) = hi;
        }
    }
}

// ---------------------------------------------------------------------------
// Flash attention with tf32 mma.sync tensor cores (unchanged from R2).
// ---------------------------------------------------------------------------
#define QS_STRIDE 68

__global__ __launch_bounds__(256) void attn_tf32(
    const float* __restrict__ qkv, const unsigned char* __restrict__ kpm,
    float* __restrict__ outp)
{
    extern __shared__ uint32_t sm[];
    uint32_t* Qs  = sm;                      // [128][68] tf32 bits
    uint32_t* Ks  = Qs  + 128 * QS_STRIDE;   // [64][68]  key-major
    uint32_t* Vst = Ks  +  64 * QS_STRIDE;   // [64][68]  d-major (V transposed)
    uint32_t* Ps  = Vst +  64 * QS_STRIDE;   // [128][68]
    float* maskAdd = (float*)(Ps + 128 * QS_STRIDE);  // [64]

    const int tid  = threadIdx.x;
    const int w    = tid >> 5;
    const int lane = tid & 31;
    const int gr   = lane >> 2;
    const int tg   = lane & 3;
    const int q0   = w * 16;
    const int m0   = blockIdx.x * 128;
    const int bh   = blockIdx.y;
    const int b    = bh >> 4;
    const int h    = bh & 15;
    const int hoff = h * 64;

    #pragma unroll
    for (int p = 0; p < 8; p++) {
        int idx = tid + p * 256;
        int r = idx >> 4, c4 = (idx & 15) * 4;
        float4 v = *(const float4*)(qkv + (size_t)((m0 + r) * BDIM + b) * E3 + hoff + c4);
        Qs[r * QS_STRIDE + c4 + 0] = f2tf(v.x);
        Qs[r * QS_STRIDE + c4 + 1] = f2tf(v.y);
        Qs[r * QS_STRIDE + c4 + 2] = f2tf(v.z);
        Qs[r * QS_STRIDE + c4 + 3] = f2tf(v.w);
    }

    float o[8][4] = {};
    float m_lo = -INFINITY, m_hi = -INFINITY;
    float l_lo = 0.f, l_hi = 0.f;

    for (int t = 0; t < LDIM / 64; t++) {
        const int s0 = t * 64;
        __syncthreads();

        #pragma unroll
        for (int p = 0; p < 4; p++) {
            int idx = tid + p * 256;
            int r = idx >> 4, c4 = (idx & 15) * 4;
            size_t base = (size_t)((s0 + r) * BDIM + b) * E3 + hoff + c4;
            float4 kv = *(const float4*)(qkv + base + EDIM);
            float4 vv = *(const float4*)(qkv + base + 2 * EDIM);
            Ks[r * QS_STRIDE + c4 + 0] = f2tf(kv.x);
            Ks[r * QS_STRIDE + c4 + 1] = f2tf(kv.y);
            Ks[r * QS_STRIDE + c4 + 2] = f2tf(kv.z);
            Ks[r * QS_STRIDE + c4 + 3] = f2tf(kv.w);
            Vst[(c4 + 0) * QS_STRIDE + r] = f2tf(vv.x);
            Vst[(c4 + 1) * QS_STRIDE + r] = f2tf(vv.y);
            Vst[(c4 + 2) * QS_STRIDE + r] = f2tf(vv.z);
            Vst[(c4 + 3) * QS_STRIDE + r] = f2tf(vv.w);
        }
        if (tid < 64)
            maskAdd[tid] = kpm[(size_t)(s0 + tid) * BDIM + b] ? -INFINITY : 0.f;
        __syncthreads();

        float c[8][4] = {};
        #pragma unroll
        for (int k8 = 0; k8 < 64; k8 += 8) {
            uint32_t a0 = Qs[(q0 + gr)     * QS_STRIDE + k8 + tg];
            uint32_t a1 = Qs[(q0 + gr + 8) * QS_STRIDE + k8 + tg];
            uint32_t a2 = Qs[(q0 + gr)     * QS_STRIDE + k8 + tg + 4];
            uint32_t a3 = Qs[(q0 + gr + 8) * QS_STRIDE + k8 + tg + 4];
            #pragma unroll
            for (int j = 0; j < 8; j++) {
                uint32_t b0 = Ks[(8 * j + gr) * QS_STRIDE + k8 + tg];
                uint32_t b1 = Ks[(8 * j + gr) * QS_STRIDE + k8 + tg + 4];
                mma_tf32(c[j], a0, a1, a2, a3, b0, b1);
            }
        }

        #pragma unroll
        for (int j = 0; j < 8; j++) {
            float ma0 = maskAdd[8 * j + 2 * tg];
            float ma1 = maskAdd[8 * j + 2 * tg + 1];
            c[j][0] += ma0; c[j][1] += ma1;
            c[j][2] += ma0; c[j][3] += ma1;
        }

        float mx_lo = -INFINITY, mx_hi = -INFINITY;
        #pragma unroll
        for (int j = 0; j < 8; j++) {
            mx_lo = fmaxf(mx_lo, fmaxf(c[j][0], c[j][1]));
            mx_hi = fmaxf(mx_hi, fmaxf(c[j][2], c[j][3]));
        }
        mx_lo = fmaxf(mx_lo, __shfl_xor_sync(0xffffffffu, mx_lo, 1));
        mx_lo = fmaxf(mx_lo, __shfl_xor_sync(0xffffffffu, mx_lo, 2));
        mx_hi = fmaxf(mx_hi, __shfl_xor_sync(0xffffffffu, mx_hi, 1));
        mx_hi = fmaxf(mx_hi, __shfl_xor_sync(0xffffffffu, mx_hi, 2));

        float mn_lo = fmaxf(m_lo, mx_lo);
        float mn_hi = fmaxf(m_hi, mx_hi);
        float mr_lo = (mn_lo == -INFINITY) ? 0.f : mn_lo;
        float mr_hi = (mn_hi == -INFINITY) ? 0.f : mn_hi;

        float sum_lo = 0.f, sum_hi = 0.f;
        #pragma unroll
        for (int j = 0; j < 8; j++) {
            float p0 = __expf(c[j][0] - mr_lo);
            float p1 = __expf(c[j][1] - mr_lo);
            float p2 = __expf(c[j][2] - mr_hi);
            float p3 = __expf(c[j][3] - mr_hi);
            sum_lo += p0 + p1;
            sum_hi += p2 + p3;
            uint2 lo; lo.x = f2tf(p0); lo.y = f2tf(p1);
            *(uint2*)&Ps[(q0 + gr)     * QS_STRIDE + 8 * j + 2 * tg] = lo;
            uint2 hi; hi.x = f2tf(p2); hi.y = f2tf(p3);
            *(uint2*)&Ps[(q0 + gr + 8) * QS_STRIDE + 8 * j + 2 * tg] = hi;
        }
        sum_lo += __shfl_xor_sync(0xffffffffu, sum_lo, 1);
        sum_lo += __shfl_xor_sync(0xffffffffu, sum_lo, 2);
        sum_hi += __shfl_xor_sync(0xffffffffu, sum_hi, 1);
        sum_hi += __shfl_xor_sync(0xffffffffu, sum_hi, 2);

        float sc_lo = (m_lo == -INFINITY) ? 0.f : __expf(m_lo - mr_lo);
        float sc_hi = (m_hi == -INFINITY) ? 0.f : __expf(m_hi - mr_hi);
        l_lo = l_lo * sc_lo + sum_lo;
        l_hi = l_hi * sc_hi + sum_hi;
        m_lo = mn_lo;
        m_hi = mn_hi;

        #pragma unroll
        for (int j = 0; j < 8; j++) {
            o[j][0] *= sc_lo; o[j][1] *= sc_lo;
            o[j][2] *= sc_hi; o[j][3] *= sc_hi;
        }
        __syncwarp();

        #pragma unroll
        for (int k8 = 0; k8 < 64; k8 += 8) {
            uint32_t a0 = Ps[(q0 + gr)     * QS_STRIDE + k8 + tg];
            uint32_t a1 = Ps[(q0 + gr + 8) * QS_STRIDE + k8 + tg];
            uint32_t a2 = Ps[(q0 + gr)     * QS_STRIDE + k8 + tg + 4];
            uint32_t a3 = Ps[(q0 + gr + 8) * QS_STRIDE + k8 + tg + 4];
            #pragma unroll
            for (int j = 0; j < 8; j++) {
                uint32_t b0 = Vst[(8 * j + gr) * QS_STRIDE + k8 + tg];
                uint32_t b1 = Vst[(8 * j + gr) * QS_STRIDE + k8 + tg + 4];
                mma_tf32(o[j], a0, a1, a2, a3, b0, b1);
            }
        }
    }

    float il_lo = 1.f / l_lo;
    float il_hi = 1.f / l_hi;
    #pragma unroll
    for (int j = 0; j < 8; j++) {
        float2 vlo = make_float2(o[j][0] * il_lo, o[j][1] * il_lo);
        *(float2*)(outp + (size_t)((m0 + q0 + gr) * BDIM + b) * EDIM
                   + hoff + 8 * j + 2 * tg) = vlo;
        float2 vhi = make_float2(o[j][2] * il_hi, o[j][3] * il_hi);
        *(float2*)(outp + (size_t)((m0 + q0 + gr + 8) * BDIM + b) * EDIM
                   + hoff + 8 * j + 2 * tg) = vhi;
    }
}

// ---------------------------------------------------------------------------
extern "C" void kernel_launch(void* const* d_in, const int* in_sizes, int n_in,
                              void* d_out, int out_size)
{
    const float* x    = (const float*)d_in[0];
    const float* win  = (const float*)d_in[1];
    const float* bin  = (const float*)d_in[2];
    const float* wout = (const float*)d_in[3];
    const float* bout = (const float*)d_in[4];
    const unsigned char* kpm = (const unsigned char*)d_in[5];
    float* out = (float*)d_out;

    float *qkv_ptr, *attn_ptr;
    cudaGetSymbolAddress((void**)&qkv_ptr,  g_qkv);
    cudaGetSymbolAddress((void**)&attn_ptr, g_attn);

    // 1) QKV projection, tf32 tensor (q pre-scaled by D^-0.5 in epilogue)
    {
        dim3 grid(E3 / 128, MROWS / 128);
        gemm_tf32<EDIM><<<grid, 256>>>(x, win, bin, qkv_ptr, E3, EDIM);
    }

    // 2) Flash attention (tf32 tensor cores)
    {
        int smem = (128 * QS_STRIDE + 64 * QS_STRIDE + 64 * QS_STRIDE
                    + 128 * QS_STRIDE) * (int)sizeof(uint32_t)
                   + 64 * (int)sizeof(float);   // 104704 B
        cudaFuncSetAttribute(attn_tf32, cudaFuncAttributeMaxDynamicSharedMemorySize, smem);
        dim3 grid(LDIM / 128, BDIM * HDIM);
        attn_tf32<<<grid, 256, smem>>>(qkv_ptr, kpm, attn_ptr);
    }

    // 3) Output projection, tf32 tensor
    {
        dim3 grid(EDIM / 128, MROWS / 128);
        gemm_tf32<0><<<grid, 256>>>(attn_ptr, wout, bout, out, EDIM, EDIM);
    }
}

// round 12
// speedup vs baseline: 3.6812x; 1.0363x over previous
#include <cuda_runtime.h>
#include <math.h>
#include <stdint.h>

// Problem dims (fixed by the benchmark)
#define LDIM 2048
#define BDIM 4
#define EDIM 1024
#define HDIM 16
#define DDIM 64
#define MROWS (LDIM * BDIM)   // 8192
#define E3    (3 * EDIM)      // 3072

// Scratch (allocation-free rule: __device__ globals)
__device__ float g_qkv[(size_t)MROWS * E3];    // [L*B, 3E], q pre-scaled
__device__ float g_attn[(size_t)MROWS * EDIM]; // [L*B, E]

// ---------------------------------------------------------------------------
// tf32 helpers
// ---------------------------------------------------------------------------
__device__ __forceinline__ uint32_t f2tf(float f) {
    uint32_t u;
    asm("cvt.rna.tf32.f32 %0, %1;" : "=r"(u) : "f"(f));
    return u;
}

__device__ __forceinline__ void mma_tf32(float c[4],
    uint32_t a0, uint32_t a1, uint32_t a2, uint32_t a3,
    uint32_t b0, uint32_t b1)
{
    asm volatile(
        "mma.sync.aligned.m16n8k8.row.col.f32.tf32.tf32.f32 "
        "{%0,%1,%2,%3}, {%4,%5,%6,%7}, {%8,%9}, {%0,%1,%2,%3};\n"
        : "+f"(c[0]), "+f"(c[1]), "+f"(c[2]), "+f"(c[3])
        : "r"(a0), "r"(a1), "r"(a2), "r"(a3), "r"(b0), "r"(b1));
}

// Paired-column permutation: within each 8-col mma block, cols (t, t+4)
// land at adjacent words (2t, 2t+1)  ->  fragment pair = one LDS.64.
// phys(c) = (c & ~7) | ((c & 3) << 1) | ((c >> 2) & 1)
__device__ __forceinline__ int permbase4(int c4) {  // for float4 at col c4 (c4 % 4 == 0); elements at +0,+2,+4,+6
    return (c4 & ~7) | ((c4 >> 2) & 1);
}

// ---------------------------------------------------------------------------
// tf32 tensor GEMM: C[m,n] = sum_k A[m,k]*W[n,k] + bias[n]
// CTA 128x128, BK=16, 8 warps each m64 x n32. Double-buffered smem.
// Stride GS=24 (== 8 mod 32): paired LDS.64 fragment loads conflict-free.
// ---------------------------------------------------------------------------
#define GS 24

template <int SCALE_COLS>
__global__ __launch_bounds__(256) void gemm_tf32(
    const float* __restrict__ A, const float* __restrict__ W,
    const float* __restrict__ bias, float* __restrict__ C,
    int Nn, int Kn)
{
    __shared__ uint32_t As[2][128 * GS];
    __shared__ uint32_t Bs[2][128 * GS];

    const int tid  = threadIdx.x;
    const int w    = tid >> 5;
    const int lane = tid & 31;
    const int gr   = lane >> 2;
    const int tg   = lane & 3;
    const int wm   = (w >> 2) * 64;   // 0 or 64
    const int wn   = (w & 3) * 32;    // 0,32,64,96
    const int n0   = blockIdx.x * 128;
    const int m0   = blockIdx.y * 128;

    const int r0 = tid >> 2;              // 0..63
    const int r1 = r0 + 64;               // 64..127
    const int c4 = (tid & 3) * 4;         // 0,4,8,12
    const int pb = permbase4(c4);

    const float* Ap0 = A + (size_t)(m0 + r0) * Kn + c4;
    const float* Ap1 = A + (size_t)(m0 + r1) * Kn + c4;
    const float* Wp0 = W + (size_t)(n0 + r0) * Kn + c4;
    const float* Wp1 = W + (size_t)(n0 + r1) * Kn + c4;

    float acc[4][4][4] = {};

    const int nK = Kn >> 4;
    float4 av0 = *(const float4*)Ap0;
    float4 av1 = *(const float4*)Ap1;
    float4 wv0 = *(const float4*)Wp0;
    float4 wv1 = *(const float4*)Wp1;

    for (int kt = 0; kt < nK; kt++) {
        const int buf = kt & 1;
        // stage (tf32-convert, permuted scalar stores)
        {
            uint32_t* a0p = &As[buf][r0 * GS + pb];
            a0p[0] = f2tf(av0.x); a0p[2] = f2tf(av0.y);
            a0p[4] = f2tf(av0.z); a0p[6] = f2tf(av0.w);
            uint32_t* a1p = &As[buf][r1 * GS + pb];
            a1p[0] = f2tf(av1.x); a1p[2] = f2tf(av1.y);
            a1p[4] = f2tf(av1.z); a1p[6] = f2tf(av1.w);
            uint32_t* b0p = &Bs[buf][r0 * GS + pb];
            b0p[0] = f2tf(wv0.x); b0p[2] = f2tf(wv0.y);
            b0p[4] = f2tf(wv0.z); b0p[6] = f2tf(wv0.w);
            uint32_t* b1p = &Bs[buf][r1 * GS + pb];
            b1p[0] = f2tf(wv1.x); b1p[2] = f2tf(wv1.y);
            b1p[4] = f2tf(wv1.z); b1p[6] = f2tf(wv1.w);
        }
        __syncthreads();

        // prefetch next BK16 tile
        if (kt + 1 < nK) {
            const int ko = (kt + 1) << 4;
            av0 = *(const float4*)(Ap0 + ko);
            av1 = *(const float4*)(Ap1 + ko);
            wv0 = *(const float4*)(Wp0 + ko);
            wv1 = *(const float4*)(Wp1 + ko);
        }

        // compute: 2 k8 steps, LDS.64 paired fragments
        #pragma unroll
        for (int k8 = 0; k8 < 16; k8 += 8) {
            uint2 alo[4], ahi[4], bb[4];
            #pragma unroll
            for (int i = 0; i < 4; i++) {
                const int mr = wm + 16 * i + gr;
                alo[i] = *(const uint2*)&As[buf][(mr)     * GS + k8 + 2 * tg];
                ahi[i] = *(const uint2*)&As[buf][(mr + 8) * GS + k8 + 2 * tg];
            }
            #pragma unroll
            for (int j = 0; j < 4; j++) {
                const int nr = wn + 8 * j + gr;
                bb[j] = *(const uint2*)&Bs[buf][nr * GS + k8 + 2 * tg];
            }
            #pragma unroll
            for (int i = 0; i < 4; i++)
                #pragma unroll
                for (int j = 0; j < 4; j++)
                    mma_tf32(acc[i][j], alo[i].x, ahi[i].x, alo[i].y, ahi[i].y,
                             bb[j].x, bb[j].y);
        }
    }

    // epilogue: bias + optional q-scaling
    #pragma unroll
    for (int i = 0; i < 4; i++) {
        const int row = m0 + wm + 16 * i + gr;
        #pragma unroll
        for (int j = 0; j < 4; j++) {
            const int col = n0 + wn + 8 * j + 2 * tg;
            const float b0v = bias[col], b1v = bias[col + 1];
            float s = (SCALE_COLS > 0 && col < SCALE_COLS) ? 0.125f : 1.0f;
            float2 lo = make_float2((acc[i][j][0] + b0v) * s,
                                    (acc[i][j][1] + b1v) * s);
            float2 hi = make_float2((acc[i][j][2] + b0v) * s,
                                    (acc[i][j][3] + b1v) * s);
            *(float2*)(C + (size_t)row * Nn + col) = lo;
            *(float2*)(C + (size_t)(row + 8) * Nn + col) = hi;
        }
    }
}

// ---------------------------------------------------------------------------
// Flash attention, tf32 mma.sync.
//  - Qs/Ks paired-column (LDS.64 fragments), stride 72 (== 8 mod 32).
//  - Vs key-major un-permuted: STS.128 staging, conflict-free scalar b-loads.
//  - P kept in registers; PV A-fragments built with quad shuffles (no Ps smem).
//  - 74 KB smem -> 2 CTAs/SM.
// ---------------------------------------------------------------------------
#define AS2 72

__global__ __launch_bounds__(256, 2) void attn_tf32(
    const float* __restrict__ qkv, const unsigned char* __restrict__ kpm,
    float* __restrict__ outp)
{
    extern __shared__ uint32_t sm[];
    uint32_t* Qs = sm;                  // [128][72] permuted tf32
    uint32_t* Ks = Qs + 128 * AS2;      // [64][72]  permuted, key rows
    uint32_t* Vs = Ks + 64 * AS2;       // [64][72]  plain, key rows
    float* maskAdd = (float*)(Vs + 64 * AS2);   // [64]

    const int tid  = threadIdx.x;
    const int w    = tid >> 5;
    const int lane = tid & 31;
    const int gr   = lane >> 2;
    const int tg   = lane & 3;
    const int q0   = w * 16;
    const int m0   = blockIdx.x * 128;
    const int bh   = blockIdx.y;
    const int b    = bh >> 4;
    const int h    = bh & 15;
    const int hoff = h * 64;
    const int sl0  = tg >> 1;           // quad src sub-lane
    const int podd = tg & 1;

    // ---- stage Q (permuted); q pre-scaled by D^-0.5 in projection ----
    #pragma unroll
    for (int p = 0; p < 8; p++) {
        int idx = tid + p * 256;
        int r = idx >> 4, c4 = (idx & 15) * 4;
        int pbq = permbase4(c4);
        float4 v = *(const float4*)(qkv + (size_t)((m0 + r) * BDIM + b) * E3 + hoff + c4);
        uint32_t* qp = &Qs[r * AS2 + pbq];
        qp[0] = f2tf(v.x); qp[2] = f2tf(v.y); qp[4] = f2tf(v.z); qp[6] = f2tf(v.w);
    }

    float o[8][4] = {};
    float m_lo = -INFINITY, m_hi = -INFINITY;
    float l_lo = 0.f, l_hi = 0.f;

    for (int t = 0; t < LDIM / 64; t++) {
        const int s0 = t * 64;
        __syncthreads();   // prior iter's reads of Ks/Vs complete

        // ---- stage K (permuted) and V (plain, key-major) ----
        #pragma unroll
        for (int p = 0; p < 4; p++) {
            int idx = tid + p * 256;
            int r = idx >> 4, c4 = (idx & 15) * 4;
            int pbk = permbase4(c4);
            size_t base = (size_t)((s0 + r) * BDIM + b) * E3 + hoff + c4;
            float4 kv = *(const float4*)(qkv + base + EDIM);
            float4 vv = *(const float4*)(qkv + base + 2 * EDIM);
            uint32_t* kp = &Ks[r * AS2 + pbk];
            kp[0] = f2tf(kv.x); kp[2] = f2tf(kv.y); kp[4] = f2tf(kv.z); kp[6] = f2tf(kv.w);
            uint4 vu;
            vu.x = f2tf(vv.x); vu.y = f2tf(vv.y); vu.z = f2tf(vv.z); vu.w = f2tf(vv.w);
            *(uint4*)&Vs[r * AS2 + c4] = vu;
        }
        if (tid < 64)
            maskAdd[tid] = kpm[(size_t)(s0 + tid) * BDIM + b] ? -INFINITY : 0.f;
        __syncthreads();

        // ---- S = Q K^T : m16 x n64 x k64 per warp (LDS.64 fragments) ----
        float c[8][4] = {};
        #pragma unroll
        for (int k8 = 0; k8 < 64; k8 += 8) {
            uint2 alo = *(const uint2*)&Qs[(q0 + gr)     * AS2 + k8 + 2 * tg];
            uint2 ahi = *(const uint2*)&Qs[(q0 + gr + 8) * AS2 + k8 + 2 * tg];
            #pragma unroll
            for (int j = 0; j < 8; j++) {
                uint2 bb = *(const uint2*)&Ks[(8 * j + gr) * AS2 + k8 + 2 * tg];
                mma_tf32(c[j], alo.x, ahi.x, alo.y, ahi.y, bb.x, bb.y);
            }
        }

        // ---- key-padding mask ----
        #pragma unroll
        for (int j = 0; j < 8; j++) {
            float ma0 = maskAdd[8 * j + 2 * tg];
            float ma1 = maskAdd[8 * j + 2 * tg + 1];
            c[j][0] += ma0; c[j][1] += ma1;
            c[j][2] += ma0; c[j][3] += ma1;
        }

        // ---- online softmax ----
        float mx_lo = -INFINITY, mx_hi = -INFINITY;
        #pragma unroll
        for (int j = 0; j < 8; j++) {
            mx_lo = fmaxf(mx_lo, fmaxf(c[j][0], c[j][1]));
            mx_hi = fmaxf(mx_hi, fmaxf(c[j][2], c[j][3]));
        }
        mx_lo = fmaxf(mx_lo, __shfl_xor_sync(0xffffffffu, mx_lo, 1));
        mx_lo = fmaxf(mx_lo, __shfl_xor_sync(0xffffffffu, mx_lo, 2));
        mx_hi = fmaxf(mx_hi, __shfl_xor_sync(0xffffffffu, mx_hi, 1));
        mx_hi = fmaxf(mx_hi, __shfl_xor_sync(0xffffffffu, mx_hi, 2));

        float mn_lo = fmaxf(m_lo, mx_lo);
        float mn_hi = fmaxf(m_hi, mx_hi);
        float mr_lo = (mn_lo == -INFINITY) ? 0.f : mn_lo;
        float mr_hi = (mn_hi == -INFINITY) ? 0.f : mn_hi;

        uint32_t cp[8][4];   // tf32 bits of P (register-resident)
        float sum_lo = 0.f, sum_hi = 0.f;
        #pragma unroll
        for (int j = 0; j < 8; j++) {
            float p0 = __expf(c[j][0] - mr_lo);
            float p1 = __expf(c[j][1] - mr_lo);
            float p2 = __expf(c[j][2] - mr_hi);
            float p3 = __expf(c[j][3] - mr_hi);
            sum_lo += p0 + p1;
            sum_hi += p2 + p3;
            cp[j][0] = f2tf(p0); cp[j][1] = f2tf(p1);
            cp[j][2] = f2tf(p2); cp[j][3] = f2tf(p3);
        }
        sum_lo += __shfl_xor_sync(0xffffffffu, sum_lo, 1);
        sum_lo += __shfl_xor_sync(0xffffffffu, sum_lo, 2);
        sum_hi += __shfl_xor_sync(0xffffffffu, sum_hi, 1);
        sum_hi += __shfl_xor_sync(0xffffffffu, sum_hi, 2);

        float sc_lo = (m_lo == -INFINITY) ? 0.f : __expf(m_lo - mr_lo);
        float sc_hi = (m_hi == -INFINITY) ? 0.f : __expf(m_hi - mr_hi);
        l_lo = l_lo * sc_lo + sum_lo;
        l_hi = l_hi * sc_hi + sum_hi;
        m_lo = mn_lo;
        m_hi = mn_hi;

        #pragma unroll
        for (int j = 0; j < 8; j++) {
            o[j][0] *= sc_lo; o[j][1] *= sc_lo;
            o[j][2] *= sc_hi; o[j][3] *= sc_hi;
        }

        // ---- O += P V : P re-fragmented via quad shuffles ----
        #pragma unroll
        for (int j = 0; j < 8; j++) {
            uint32_t e, od, a0, a1, a2, a3;
            e  = __shfl_sync(0xffffffffu, cp[j][0], sl0, 4);
            od = __shfl_sync(0xffffffffu, cp[j][1], sl0, 4);
            a0 = podd ? od : e;
            e  = __shfl_sync(0xffffffffu, cp[j][0], sl0 + 2, 4);
            od = __shfl_sync(0xffffffffu, cp[j][1], sl0 + 2, 4);
            a2 = podd ? od : e;
            e  = __shfl_sync(0xffffffffu, cp[j][2], sl0, 4);
            od = __shfl_sync(0xffffffffu, cp[j][3], sl0, 4);
            a1 = podd ? od : e;
            e  = __shfl_sync(0xffffffffu, cp[j][2], sl0 + 2, 4);
            od = __shfl_sync(0xffffffffu, cp[j][3], sl0 + 2, 4);
            a3 = podd ? od : e;

            const int k8 = 8 * j;
            #pragma unroll
            for (int jj = 0; jj < 8; jj++) {
                uint32_t b0 = Vs[(k8 + tg)     * AS2 + 8 * jj + gr];
                uint32_t b1 = Vs[(k8 + tg + 4) * AS2 + 8 * jj + gr];
                mma_tf32(o[jj], a0, a1, a2, a3, b0, b1);
            }
        }
    }

    // ---- normalize + write out [L*B, E] at head offset ----
    float il_lo = 1.f / l_lo;
    float il_hi = 1.f / l_hi;
    #pragma unroll
    for (int j = 0; j < 8; j++) {
        float2 vlo = make_float2(o[j][0] * il_lo, o[j][1] * il_lo);
        *(float2*)(outp + (size_t)((m0 + q0 + gr) * BDIM + b) * EDIM
                   + hoff + 8 * j + 2 * tg) = vlo;
        float2 vhi = make_float2(o[j][2] * il_hi, o[j][3] * il_hi);
        *(float2*)(outp + (size_t)((m0 + q0 + gr + 8) * BDIM + b) * EDIM
                   + hoff + 8 * j + 2 * tg) = vhi;
    }
}

// ---------------------------------------------------------------------------
extern "C" void kernel_launch(void* const* d_in, const int* in_sizes, int n_in,
                              void* d_out, int out_size)
{
    const float* x    = (const float*)d_in[0];
    const float* win  = (const float*)d_in[1];
    const float* bin  = (const float*)d_in[2];
    const float* wout = (const float*)d_in[3];
    const float* bout = (const float*)d_in[4];
    const unsigned char* kpm = (const unsigned char*)d_in[5];
    float* out = (float*)d_out;

    float *qkv_ptr, *attn_ptr;
    cudaGetSymbolAddress((void**)&qkv_ptr,  g_qkv);
    cudaGetSymbolAddress((void**)&attn_ptr, g_attn);

    // 1) QKV projection (tf32 tensor; q pre-scaled by D^-0.5 in epilogue)
    {
        dim3 grid(E3 / 128, MROWS / 128);
        gemm_tf32<EDIM><<<grid, 256>>>(x, win, bin, qkv_ptr, E3, EDIM);
    }

    // 2) Flash attention (tf32 tensor, 2 CTAs/SM)
    {
        int smem = (128 * AS2 + 64 * AS2 + 64 * AS2) * (int)sizeof(uint32_t)
                   + 64 * (int)sizeof(float);   // 73984 B
        cudaFuncSetAttribute(attn_tf32, cudaFuncAttributeMaxDynamicSharedMemorySize, smem);
        dim3 grid(LDIM / 128, BDIM * HDIM);
        attn_tf32<<<grid, 256, smem>>>(qkv_ptr, kpm, attn_ptr);
    }

    // 3) Output projection (tf32 tensor)
    {
        dim3 grid(EDIM / 128, MROWS / 128);
        gemm_tf32<0><<<grid, 256>>>(attn_ptr, wout, bout, out, EDIM, EDIM);
    }
}